// round 13
// baseline (speedup 1.0000x reference)
#include <cuda_runtime.h>

#define BB 4096
#define TT 64
#define T1 65
#define HH 64
#define PP 50
#define VV 32
#define BT 16
#define NBLK (BB / BT) /* 256 */

#define SMEM_FLOATS 27680
#define SMEM_BYTES (SMEM_FLOATS * 4)

typedef unsigned long long ull;

// scratch (device globals; no allocation allowed)
__device__ float g_table[3 * 32 * 64];
__device__ float g_phonb[3 * BB * 64];
__device__ float g_part[2 * NBLK];
__device__ int   g_cs[BB * T1];
__device__ int   g_flag;

// ---- helpers --------------------------------------------------------------
__device__ __forceinline__ ull fma2(ull a, ull b, ull c) {
    asm("fma.rn.f32x2 %0, %1, %2, %0;" : "+l"(c) : "l"(a), "l"(b));
    return c;
}
__device__ __forceinline__ ull pack2(float a, float b) {
    ull d;
    asm("mov.b64 %0, {%1, %2};" : "=l"(d)
        : "r"(__float_as_uint(a)), "r"(__float_as_uint(b)));
    return d;
}
__device__ __forceinline__ ull dup2(float v) {
    ull d;
    unsigned int u = __float_as_uint(v);
    asm("mov.b64 %0, {%1, %1};" : "=l"(d) : "r"(u));
    return d;
}
__device__ __forceinline__ void unpack2(ull d, float& a, float& b) {
    unsigned int x, y;
    asm("mov.b64 {%0, %1}, %2;" : "=r"(x), "=r"(y) : "l"(d));
    a = __uint_as_float(x);
    b = __uint_as_float(y);
}
__device__ __forceinline__ float sigf(float x) {
    float e = __expf(-x);
    return __fdividef(1.f, 1.f + e);
}
__device__ __forceinline__ float tanhfast(float x) {
    float e = __expf(-2.f * x);
    return __fdividef(2.f, 1.f + e) - 1.f;
}
// pair-scoped barrier: warps {2m, 2m+1} (64 threads), ids 1..4
__device__ __forceinline__ void pair_bar(int m) {
    asm volatile("bar.sync %0, 64;" :: "r"(m + 1) : "memory");
}

// -------------------------------------------------------------------------
// Kernel 0a: detect char_seq dtype (odd-word OR; 0 <=> int64 storage)
// -------------------------------------------------------------------------
__global__ void detect_kernel(const int* __restrict__ src, int nelem) {
    __shared__ int sh[1024];
    int acc = 0;
    for (int i = threadIdx.x; i < nelem; i += 1024)
        if (i & 1) acc |= src[i];
    sh[threadIdx.x] = acc;
    __syncthreads();
    for (int s = 512; s > 0; s >>= 1) {
        if (threadIdx.x < s) sh[threadIdx.x] |= sh[threadIdx.x + s];
        __syncthreads();
    }
    if (threadIdx.x == 0) g_flag = sh[0];
}

__global__ void convert_kernel(const void* __restrict__ src) {
    int i = blockIdx.x * blockDim.x + threadIdx.x;
    if (i >= BB * T1) return;
    if (g_flag != 0) g_cs[i] = ((const int*)src)[i];
    else             g_cs[i] = (int)((const long long*)src)[i];
}

// -------------------------------------------------------------------------
// Kernel 1: char table  table[g][c][j] = sum_k emb[c][k] * W_gx[k][j]
// -------------------------------------------------------------------------
__global__ void table_kernel(const float* __restrict__ emb,
                             const float* __restrict__ Wrx,
                             const float* __restrict__ Wzx,
                             const float* __restrict__ Whx) {
    int idx = blockIdx.x * blockDim.x + threadIdx.x;
    if (idx >= 3 * 32 * 64) return;
    int g = idx >> 11;
    int rem = idx & 2047;
    int c = rem >> 6;
    int j = rem & 63;
    const float* W = (g == 0) ? Wrx : ((g == 1) ? Wzx : Whx);
    const float* e = emb + c * HH;
    float acc = 0.f;
#pragma unroll
    for (int k = 0; k < HH; k++) acc = fmaf(e[k], W[k * HH + j], acc);
    g_table[idx] = acc;
}

// -------------------------------------------------------------------------
// Kernel 2: phon part (f32x2 over j-pairs)
// -------------------------------------------------------------------------
__global__ void phonb_kernel(const float* __restrict__ phon,
                             const float* __restrict__ Wrx,
                             const float* __restrict__ Wzx,
                             const float* __restrict__ Whx,
                             const float* __restrict__ brx,
                             const float* __restrict__ brh,
                             const float* __restrict__ bzx,
                             const float* __restrict__ bzh,
                             const float* __restrict__ bhx,
                             const float* __restrict__ bhh) {
    int idx = blockIdx.x * blockDim.x + threadIdx.x;
    if (idx >= 3 * BB * 32) return;
    int g = idx / (BB * 32);
    int rem = idx - g * (BB * 32);
    int b = rem >> 5;
    int jp = rem & 31;
    const float* W  = (g == 0) ? Wrx : ((g == 1) ? Wzx : Whx);
    const float* bx = (g == 0) ? brx : ((g == 1) ? bzx : bhx);
    const float* bh = (g == 0) ? brh : ((g == 1) ? bzh : bhh);
    float2 x2 = *(const float2*)&bx[jp * 2];
    float2 h2 = *(const float2*)&bh[jp * 2];
    ull acc = pack2(x2.x + h2.x, x2.y + h2.y);
    const float* ph = phon + b * PP;
#pragma unroll
    for (int p = 0; p < PP; p++) {
        ull d = dup2(ph[p]);
        ull w = *(const ull*)&W[(HH + p) * HH + jp * 2];
        acc = fma2(d, w, acc);
    }
    float a0, a1;
    unpack2(acc, a0, a1);
    *(float2*)&g_phonb[g * (BB * 64) + b * 64 + jp * 2] = make_float2(a0, a1);
}

// -------------------------------------------------------------------------
// Kernel 3: persistent fused GRU recurrence + projection + NLL.
//   Passes A/B use DUP-IN-SMEM layouts: hdup[row][k]=(h,h),
//   rhdup[row][k]=(rh,rh) so fma2 operands come directly from LDS
//   (weight = natural contiguous pair, h = dup broadcast): zero MOVs.
//   Pair-scoped barriers; pass C row-pair layout (sHp).
//   SMEM MAP (floats):
//     sWa 0..8191 | sWh 8192..12287 | sWp 12288..14335 | sTab 14336..20479
//     hdup 20480..22527 | rhdup 22528..24575 | sHp 24576..25599
//     sZ 25600..26623 | sCS 26624..27663 (1040 ints!) | sRed 27664..27679
// -------------------------------------------------------------------------
__global__ __launch_bounds__(256, 2)
void gru_kernel(const float* __restrict__ Wrh,
                const float* __restrict__ Wzh,
                const float* __restrict__ Whh,
                const float* __restrict__ Wproj,
                const float* __restrict__ bproj,
                float* __restrict__ out) {
    extern __shared__ float sm[];
    float* sWa   = sm;             // [64][128]: W_rh | W_zh, k-major
    float* sWh   = sm + 8192;      // [64][64]
    float* sWp   = sm + 12288;     // [64][32]
    float* sTab  = sm + 14336;     // [3][32][64]
    float* hdup  = sm + 20480;     // [16 rows][64 k][2] (h,h)
    float* rhdup = sm + 22528;     // [16][64][2] (rh,rh)
    float* sHp   = sm + 24576;     // [8 pairs][64 k][2] row-pair (pass C)
    float* sZ    = sm + 25600;     // [16][64]
    int*   sCS   = (int*)(sm + 26624); // [16][65] = 1040 ints
    float* sRed  = sm + 27664;     // [16]

    const int tid = threadIdx.x;
    const int b0 = blockIdx.x * BT;

    // cooperative init
    for (int i = tid; i < 8192; i += 256) {
        int k = i >> 7, j = i & 127;
        sWa[i] = (j < 64) ? Wrh[k * 64 + j] : Wzh[k * 64 + (j - 64)];
    }
    for (int i = tid; i < 4096; i += 256) sWh[i] = Whh[i];
    for (int i = tid; i < 2048; i += 256) sWp[i] = Wproj[i];
    for (int i = tid; i < 6144; i += 256) sTab[i] = g_table[i];
    for (int i = tid; i < BT * T1; i += 256) {
        int r = i / T1, t = i - r * T1;
        sCS[i] = g_cs[(b0 + r) * T1 + t];
    }
    for (int i = tid; i < 2048; i += 256) hdup[i] = 0.f;

    // thread mappings
    const int rq = tid >> 6;           // 0..3 = pair-group (rows 4rq..4rq+3)
    const int cg = tid & 63;           // 0..63
    const int gA = cg >> 5;            // pass A gate (0:r, 1:z)
    const int jjA = 2 * (cg & 31);     // pass A col base within gate
    const int sB = cg >> 5;            // pass B row-subpair
    const int cB = 2 * (cg & 31);      // pass B col base
    const int row0B = 4 * rq + 2 * sB, row1B = row0B + 1;
    const int v  = tid & 31;           // pass C vocab col
    const int rg = tid >> 5;           // 0..7 -> pair rg (rows 2rg, 2rg+1)

    float pbA[4][2];
#pragma unroll
    for (int r = 0; r < 4; r++) {
        int base = gA * (BB * 64) + (b0 + 4 * rq + r) * 64 + jjA;
        pbA[r][0] = g_phonb[base];
        pbA[r][1] = g_phonb[base + 1];
    }
    float2 pbB0 = *(const float2*)&g_phonb[2 * (BB * 64) + (b0 + row0B) * 64 + cB];
    float2 pbB1 = *(const float2*)&g_phonb[2 * (BB * 64) + (b0 + row1B) * 64 + cB];
    const float bp = bproj[v];
    float nllAcc = 0.f, cntAcc = 0.f;

    const float* wA = sWa + gA * 64 + jjA;
    const float* wB = sWh + cB;

    __syncthreads();

    for (int t = 0; t < TT; t++) {
        int cc[4];
#pragma unroll
        for (int r = 0; r < 4; r++) cc[r] = sCS[(4 * rq + r) * T1 + t];

        // ---------------- Pass A: r,z gates:  h @ [W_rh|W_zh] -------------
        // acc[r] = (col jjA, col jjA+1) for row 4rq+r; operands pure LDS.
        ull a0 = 0, a1 = 0, a2 = 0, a3 = 0;
#pragma unroll
        for (int k2 = 0; k2 < 64; k2 += 2) {
            ulonglong2 h0 = *(const ulonglong2*)&hdup[(4 * rq + 0) * 128 + 2 * k2];
            ulonglong2 h1 = *(const ulonglong2*)&hdup[(4 * rq + 1) * 128 + 2 * k2];
            ulonglong2 h2 = *(const ulonglong2*)&hdup[(4 * rq + 2) * 128 + 2 * k2];
            ulonglong2 h3 = *(const ulonglong2*)&hdup[(4 * rq + 3) * 128 + 2 * k2];
            ull w0 = *(const ull*)&wA[k2 * 128];
            ull w1 = *(const ull*)&wA[(k2 + 1) * 128];
            a0 = fma2(h0.x, w0, a0); a0 = fma2(h0.y, w1, a0);
            a1 = fma2(h1.x, w0, a1); a1 = fma2(h1.y, w1, a1);
            a2 = fma2(h2.x, w0, a2); a2 = fma2(h2.y, w1, a2);
            a3 = fma2(h3.x, w0, a3); a3 = fma2(h3.y, w1, a3);
        }
        {
            float av[4][2];
            unpack2(a0, av[0][0], av[0][1]);
            unpack2(a1, av[1][0], av[1][1]);
            unpack2(a2, av[2][0], av[2][1]);
            unpack2(a3, av[3][0], av[3][1]);
            const float* tg_ = sTab + gA * 2048;
#pragma unroll
            for (int r = 0; r < 4; r++) {
                float2 tv = *(const float2*)&tg_[cc[r] * 64 + jjA];
                float g0 = sigf(av[r][0] + tv.x + pbA[r][0]);
                float g1 = sigf(av[r][1] + tv.y + pbA[r][1]);
                int row = 4 * rq + r;
                if (gA == 0) {
                    float4 H = *(const float4*)&hdup[row * 128 + 2 * jjA]; // (hj,hj,hj1,hj1)
                    float r0 = g0 * H.x, r1 = g1 * H.z;
                    *(float4*)&rhdup[row * 128 + 2 * jjA] = make_float4(r0, r0, r1, r1);
                } else {
                    *(float2*)&sZ[row * 64 + jjA] = make_float2(g0, g1);
                }
            }
        }
        pair_bar(rq);

        // ---------------- Pass B: candidate:  (r*h) @ W_hh ----------------
        // thread = (2 rows: row0B,row1B) x (2 cols: cB,cB+1)
        ull bA = 0, bB = 0;
#pragma unroll
        for (int k2 = 0; k2 < 64; k2 += 2) {
            ulonglong2 r0 = *(const ulonglong2*)&rhdup[row0B * 128 + 2 * k2];
            ulonglong2 r1 = *(const ulonglong2*)&rhdup[row1B * 128 + 2 * k2];
            ull w0 = *(const ull*)&wB[k2 * 64];
            ull w1 = *(const ull*)&wB[(k2 + 1) * 64];
            bA = fma2(r0.x, w0, bA); bA = fma2(r0.y, w1, bA);
            bB = fma2(r1.x, w0, bB); bB = fma2(r1.y, w1, bB);
        }
        {
            float x00, x01, x10, x11;
            unpack2(bA, x00, x01);   // row0B @ cols cB, cB+1
            unpack2(bB, x10, x11);   // row1B
            float2 tb0 = *(const float2*)&sTab[4096 + cc[2 * sB] * 64 + cB];
            float2 tb1 = *(const float2*)&sTab[4096 + cc[2 * sB + 1] * 64 + cB];
            float cv00 = tanhfast(x00 + tb0.x + pbB0.x);
            float cv01 = tanhfast(x01 + tb0.y + pbB0.y);
            float cv10 = tanhfast(x10 + tb1.x + pbB1.x);
            float cv11 = tanhfast(x11 + tb1.y + pbB1.y);
            float2 z0 = *(const float2*)&sZ[row0B * 64 + cB];
            float2 z1 = *(const float2*)&sZ[row1B * 64 + cB];
            float4 Hd0 = *(const float4*)&hdup[row0B * 128 + 2 * cB];
            float4 Hd1 = *(const float4*)&hdup[row1B * 128 + 2 * cB];
            float hn00 = fmaf(z0.x, cv00 - Hd0.x, Hd0.x);
            float hn01 = fmaf(z0.y, cv01 - Hd0.z, Hd0.z);
            float hn10 = fmaf(z1.x, cv10 - Hd1.x, Hd1.x);
            float hn11 = fmaf(z1.y, cv11 - Hd1.z, Hd1.z);
            *(float4*)&hdup[row0B * 128 + 2 * cB] = make_float4(hn00, hn00, hn01, hn01);
            *(float4*)&hdup[row1B * 128 + 2 * cB] = make_float4(hn10, hn10, hn11, hn11);
            // row-pair layout for pass C: pair = row0B>>1 = 2rq+sB
            *(float4*)&sHp[(2 * rq + sB) * 128 + 2 * cB] =
                make_float4(hn00, hn10, hn01, hn11);
        }
        pair_bar(rq);

        // ---------------- Pass C: logits + log-softmax NLL ----------------
        ull cP = 0;
        const float* hc = sHp + rg * 128;
#pragma unroll
        for (int k4 = 0; k4 < 64; k4 += 4) {
            float4 A = *(const float4*)(hc + 2 * k4);
            float4 B = *(const float4*)(hc + 2 * k4 + 4);
            ull hp[4];
            hp[0] = pack2(A.x, A.y); hp[1] = pack2(A.z, A.w);
            hp[2] = pack2(B.x, B.y); hp[3] = pack2(B.z, B.w);
#pragma unroll
            for (int kk = 0; kk < 4; kk++) {
                ull wd = dup2(sWp[(k4 + kk) * 32 + v]);
                cP = fma2(hp[kk], wd, cP);
            }
        }
        float accC[2];
        unpack2(cP, accC[0], accC[1]);   // rows 2rg, 2rg+1
#pragma unroll
        for (int r = 0; r < 2; r++) {
            int row = 2 * rg + r;
            float lg = accC[r] + bp;
            out[((long long)(b0 + row) * TT + t) * VV + v] = lg;
            int tgt = sCS[row * T1 + t + 1];
            float m = lg;
#pragma unroll
            for (int o = 16; o > 0; o >>= 1)
                m = fmaxf(m, __shfl_xor_sync(0xffffffffu, m, o));
            float s = __expf(lg - m);
#pragma unroll
            for (int o = 16; o > 0; o >>= 1)
                s += __shfl_xor_sync(0xffffffffu, s, o);
            float lt = __shfl_sync(0xffffffffu, lg, tgt);
            if (v == 0 && tgt != 0) {
                nllAcc += m + __logf(s) - lt;
                cntAcc += 1.f;
            }
        }
        // pass C reads only pair rg's sHp rows (written in pass B by this
        // same pair-group); next pass A reads hdup (same group) -> no barrier.
    }

    // deterministic per-block loss partials
    if (v == 0) { sRed[rg] = nllAcc; sRed[8 + rg] = cntAcc; }
    __syncthreads();
    if (tid == 0) {
        float a = 0.f, c = 0.f;
#pragma unroll
        for (int i = 0; i < 8; i++) { a += sRed[i]; c += sRed[8 + i]; }
        g_part[blockIdx.x] = a;
        g_part[NBLK + blockIdx.x] = c;
    }
}

// -------------------------------------------------------------------------
// Kernel 4: final loss reduction (deterministic tree)
// -------------------------------------------------------------------------
__global__ void loss_kernel(float* __restrict__ out, long long out_size) {
    __shared__ float sa[NBLK], sc[NBLK];
    int tid = threadIdx.x;
    sa[tid] = g_part[tid];
    sc[tid] = g_part[NBLK + tid];
    __syncthreads();
    for (int s = NBLK / 2; s > 0; s >>= 1) {
        if (tid < s) { sa[tid] += sa[tid + s]; sc[tid] += sc[tid + s]; }
        __syncthreads();
    }
    if (tid == 0 && out_size > (long long)BB * TT * VV)
        out[out_size - 1] = sa[0] / fmaxf(sc[0], 1.f);
}

// -------------------------------------------------------------------------
extern "C" void kernel_launch(void* const* d_in, const int* in_sizes, int n_in,
                              void* d_out, int out_size) {
    const float* phon  = (const float*)d_in[0];
    const void*  cs    = d_in[1];
    const float* emb   = (const float*)d_in[2];
    const float* Wrx   = (const float*)d_in[3];
    const float* brx   = (const float*)d_in[4];
    const float* Wrh   = (const float*)d_in[5];
    const float* brh   = (const float*)d_in[6];
    const float* Wzx   = (const float*)d_in[7];
    const float* bzx   = (const float*)d_in[8];
    const float* Wzh   = (const float*)d_in[9];
    const float* bzh   = (const float*)d_in[10];
    const float* Whx   = (const float*)d_in[11];
    const float* bhx   = (const float*)d_in[12];
    const float* Whh   = (const float*)d_in[13];
    const float* bhh   = (const float*)d_in[14];
    const float* Wproj = (const float*)d_in[15];
    const float* bproj = (const float*)d_in[16];
    float* out = (float*)d_out;

    (void)cudaFuncSetAttribute(gru_kernel,
                               cudaFuncAttributeMaxDynamicSharedMemorySize,
                               SMEM_BYTES);

    detect_kernel<<<1, 1024>>>((const int*)cs, BB * T1);
    convert_kernel<<<(BB * T1 + 255) / 256, 256>>>(cs);
    table_kernel<<<24, 256>>>(emb, Wrx, Wzx, Whx);
    phonb_kernel<<<(3 * BB * 32 + 255) / 256, 256>>>(phon, Wrx, Wzx, Whx,
                                                     brx, brh, bzx, bzh, bhx, bhh);
    gru_kernel<<<NBLK, 256, SMEM_BYTES>>>(Wrh, Wzh, Whh, Wproj, bproj, out);
    loss_kernel<<<1, 256>>>(out, (long long)out_size);
}

// round 14
// speedup vs baseline: 1.1646x; 1.1646x over previous
#include <cuda_runtime.h>

#define BB 4096
#define TT 64
#define T1 65
#define HH 64
#define PP 50
#define VV 32
#define BT 16
#define NBLK (BB / BT) /* 256 */

#define HS 68  /* padded row stride (floats) for sH/sRH/sZ: banks shift 4/row */

#define SMEM_FLOATS 24800
#define SMEM_BYTES (SMEM_FLOATS * 4)

typedef unsigned long long ull;

// scratch (device globals; no allocation allowed)
__device__ float g_table[3 * 32 * 64];
__device__ float g_phonb[3 * BB * 64];
__device__ float g_part[2 * NBLK];
__device__ int   g_cs[BB * T1];
__device__ int   g_flag;

// ---- helpers --------------------------------------------------------------
__device__ __forceinline__ ull fma2(ull a, ull b, ull c) {
    asm("fma.rn.f32x2 %0, %1, %2, %0;" : "+l"(c) : "l"(a), "l"(b));
    return c;
}
__device__ __forceinline__ ull pack2(float a, float b) {
    ull d;
    asm("mov.b64 %0, {%1, %2};" : "=l"(d)
        : "r"(__float_as_uint(a)), "r"(__float_as_uint(b)));
    return d;
}
__device__ __forceinline__ ull dup2(float v) {
    ull d;
    unsigned int u = __float_as_uint(v);
    asm("mov.b64 %0, {%1, %1};" : "=l"(d) : "r"(u));
    return d;
}
__device__ __forceinline__ void unpack2(ull d, float& a, float& b) {
    unsigned int x, y;
    asm("mov.b64 {%0, %1}, %2;" : "=r"(x), "=r"(y) : "l"(d));
    a = __uint_as_float(x);
    b = __uint_as_float(y);
}
__device__ __forceinline__ float sigf(float x) {
    float e = __expf(-x);
    return __fdividef(1.f, 1.f + e);
}
__device__ __forceinline__ float tanhfast(float x) {
    float e = __expf(-2.f * x);
    return __fdividef(2.f, 1.f + e) - 1.f;
}

// -------------------------------------------------------------------------
// Kernel 0a: detect char_seq dtype (odd-word OR; 0 <=> int64 storage)
// -------------------------------------------------------------------------
__global__ void detect_kernel(const int* __restrict__ src, int nelem) {
    __shared__ int sh[1024];
    int acc = 0;
    for (int i = threadIdx.x; i < nelem; i += 1024)
        if (i & 1) acc |= src[i];
    sh[threadIdx.x] = acc;
    __syncthreads();
    for (int s = 512; s > 0; s >>= 1) {
        if (threadIdx.x < s) sh[threadIdx.x] |= sh[threadIdx.x + s];
        __syncthreads();
    }
    if (threadIdx.x == 0) g_flag = sh[0];
}

__global__ void convert_kernel(const void* __restrict__ src) {
    int i = blockIdx.x * blockDim.x + threadIdx.x;
    if (i >= BB * T1) return;
    if (g_flag != 0) g_cs[i] = ((const int*)src)[i];
    else             g_cs[i] = (int)((const long long*)src)[i];
}

// -------------------------------------------------------------------------
// Kernel 1: char table  table[g][c][j] = sum_k emb[c][k] * W_gx[k][j]
// -------------------------------------------------------------------------
__global__ void table_kernel(const float* __restrict__ emb,
                             const float* __restrict__ Wrx,
                             const float* __restrict__ Wzx,
                             const float* __restrict__ Whx) {
    int idx = blockIdx.x * blockDim.x + threadIdx.x;
    if (idx >= 3 * 32 * 64) return;
    int g = idx >> 11;
    int rem = idx & 2047;
    int c = rem >> 6;
    int j = rem & 63;
    const float* W = (g == 0) ? Wrx : ((g == 1) ? Wzx : Whx);
    const float* e = emb + c * HH;
    float acc = 0.f;
#pragma unroll
    for (int k = 0; k < HH; k++) acc = fmaf(e[k], W[k * HH + j], acc);
    g_table[idx] = acc;
}

// -------------------------------------------------------------------------
// Kernel 2: phon part (f32x2 over j-pairs)
// -------------------------------------------------------------------------
__global__ void phonb_kernel(const float* __restrict__ phon,
                             const float* __restrict__ Wrx,
                             const float* __restrict__ Wzx,
                             const float* __restrict__ Whx,
                             const float* __restrict__ brx,
                             const float* __restrict__ brh,
                             const float* __restrict__ bzx,
                             const float* __restrict__ bzh,
                             const float* __restrict__ bhx,
                             const float* __restrict__ bhh) {
    int idx = blockIdx.x * blockDim.x + threadIdx.x;
    if (idx >= 3 * BB * 32) return;
    int g = idx / (BB * 32);
    int rem = idx - g * (BB * 32);
    int b = rem >> 5;
    int jp = rem & 31;
    const float* W  = (g == 0) ? Wrx : ((g == 1) ? Wzx : Whx);
    const float* bx = (g == 0) ? brx : ((g == 1) ? bzx : bhx);
    const float* bh = (g == 0) ? brh : ((g == 1) ? bzh : bhh);
    float2 x2 = *(const float2*)&bx[jp * 2];
    float2 h2 = *(const float2*)&bh[jp * 2];
    ull acc = pack2(x2.x + h2.x, x2.y + h2.y);
    const float* ph = phon + b * PP;
#pragma unroll
    for (int p = 0; p < PP; p++) {
        ull d = dup2(ph[p]);
        ull w = *(const ull*)&W[(HH + p) * HH + jp * 2];
        acc = fma2(d, w, acc);
    }
    float a0, a1;
    unpack2(acc, a0, a1);
    *(float2*)&g_phonb[g * (BB * 64) + b * 64 + jp * 2] = make_float2(a0, a1);
}

// -------------------------------------------------------------------------
// Kernel 3: persistent fused GRU recurrence + projection + NLL.
//   Row-amortized blocking to cut weight LDS bytes (the measured bottleneck):
//   Pass A: warp = 16 rows x 16 cols (lane: rows {a, a+8} x 4 consec cols)
//           6 wf/k4 vs 12.  Weight ull pairs natural (zero pack MOVs).
//   Pass B: warp = 16 rows x 8 cols (lane: rows {a, a+8} x 2 cols), 6 wf/k4.
//   Pass C: unchanged warp-softmax; reads padded sH directly.
//   sH/sRH/sZ padded stride 68 -> 8-distinct-row float4 loads conflict-free.
//   2 block-wide barriers/step (cross-row sharing requires them).
//   SMEM MAP (floats): sWa 0..8191 | sWh 8192..12287 | sWp 12288..14335
//     sTab 14336..20479 | sH 20480..21567 | sRH 21568..22655
//     sZ 22656..23743 | sCS 23744..24783 (1040 ints) | sRed 24784..24799
// -------------------------------------------------------------------------
__global__ __launch_bounds__(256, 2)
void gru_kernel(const float* __restrict__ Wrh,
                const float* __restrict__ Wzh,
                const float* __restrict__ Whh,
                const float* __restrict__ Wproj,
                const float* __restrict__ bproj,
                float* __restrict__ out) {
    extern __shared__ float sm[];
    float* sWa  = sm;             // [64][128]: W_rh | W_zh, k-major
    float* sWh  = sm + 8192;      // [64][64]
    float* sWp  = sm + 12288;     // [64][32]
    float* sTab = sm + 14336;     // [3][32][64]
    float* sH   = sm + 20480;     // [16][68] padded
    float* sRH  = sm + 21568;     // [16][68]
    float* sZ   = sm + 22656;     // [16][68]
    int*   sCS  = (int*)(sm + 23744); // [16][65] = 1040 ints
    float* sRed = sm + 24784;     // [16]

    const int tid = threadIdx.x;
    const int b0 = blockIdx.x * BT;

    // cooperative init
    for (int i = tid; i < 8192; i += 256) {
        int k = i >> 7, j = i & 127;
        sWa[i] = (j < 64) ? Wrh[k * 64 + j] : Wzh[k * 64 + (j - 64)];
    }
    for (int i = tid; i < 4096; i += 256) sWh[i] = Whh[i];
    for (int i = tid; i < 2048; i += 256) sWp[i] = Wproj[i];
    for (int i = tid; i < 6144; i += 256) sTab[i] = g_table[i];
    for (int i = tid; i < BT * T1; i += 256) {
        int r = i / T1, t = i - r * T1;
        sCS[i] = g_cs[(b0 + r) * T1 + t];
    }
    for (int i = tid; i < BT * HS; i += 256) sH[i] = 0.f;

    // thread mappings
    const int w    = tid >> 5;        // warp 0..7
    const int lane = tid & 31;
    const int a    = lane & 7;        // row base: rows {a, a+8}
    const int gcol = lane >> 3;       // 0..3 col group
    // pass A: gate gA = w>>2, 16-col slice (w&3), 4 cols per lane
    const int gA = w >> 2;
    const int jA = (w & 3) * 16 + gcol * 4;
    // pass B: 8-col slice per warp, 2 cols per lane
    const int cB = 8 * w + 2 * gcol;
    // pass C: rows 2w, 2w+1, vocab col = lane
    const int v = lane;

    const int rA0 = a, rA1 = a + 8;

    float4 pbA0 = *(const float4*)&g_phonb[gA * (BB * 64) + (b0 + rA0) * 64 + jA];
    float4 pbA1 = *(const float4*)&g_phonb[gA * (BB * 64) + (b0 + rA1) * 64 + jA];
    float2 pbB0 = *(const float2*)&g_phonb[2 * (BB * 64) + (b0 + rA0) * 64 + cB];
    float2 pbB1 = *(const float2*)&g_phonb[2 * (BB * 64) + (b0 + rA1) * 64 + cB];
    const float bp = bproj[v];
    float nllAcc = 0.f, cntAcc = 0.f;

    const float* wA = sWa + gA * 64 + jA;
    const float* wB = sWh + cB;

    __syncthreads();

    for (int t = 0; t < TT; t++) {
        const int cc0 = sCS[rA0 * T1 + t];
        const int cc1 = sCS[rA1 * T1 + t];

        // ---------------- Pass A: r,z gates:  h @ [W_rh|W_zh] -------------
        // acc[row][colpair]: acc00=(jA,jA+1) acc01=(jA+2,jA+3) for rA0; 10/11 rA1
        ull a00 = 0, a01 = 0, a10 = 0, a11 = 0;
#pragma unroll
        for (int k4 = 0; k4 < 64; k4 += 4) {
            float h0v[4], h1v[4];
            *(float4*)h0v = *(const float4*)&sH[rA0 * HS + k4];
            *(float4*)h1v = *(const float4*)&sH[rA1 * HS + k4];
#pragma unroll
            for (int kk = 0; kk < 4; kk++) {
                ulonglong2 wv = *(const ulonglong2*)&wA[(k4 + kk) * 128];
                ull d0 = dup2(h0v[kk]);
                ull d1 = dup2(h1v[kk]);
                a00 = fma2(d0, wv.x, a00); a01 = fma2(d0, wv.y, a01);
                a10 = fma2(d1, wv.x, a10); a11 = fma2(d1, wv.y, a11);
            }
        }
        {
            float p00, p01, p02, p03, p10, p11, p12, p13;
            unpack2(a00, p00, p01); unpack2(a01, p02, p03);
            unpack2(a10, p10, p11); unpack2(a11, p12, p13);
            float4 tv0 = *(const float4*)&sTab[gA * 2048 + cc0 * 64 + jA];
            float4 tv1 = *(const float4*)&sTab[gA * 2048 + cc1 * 64 + jA];
            float g00 = sigf(p00 + tv0.x + pbA0.x);
            float g01 = sigf(p01 + tv0.y + pbA0.y);
            float g02 = sigf(p02 + tv0.z + pbA0.z);
            float g03 = sigf(p03 + tv0.w + pbA0.w);
            float g10 = sigf(p10 + tv1.x + pbA1.x);
            float g11 = sigf(p11 + tv1.y + pbA1.y);
            float g12 = sigf(p12 + tv1.z + pbA1.z);
            float g13 = sigf(p13 + tv1.w + pbA1.w);
            if (gA == 0) {
                float4 H0 = *(const float4*)&sH[rA0 * HS + jA];
                float4 H1 = *(const float4*)&sH[rA1 * HS + jA];
                *(float4*)&sRH[rA0 * HS + jA] =
                    make_float4(g00 * H0.x, g01 * H0.y, g02 * H0.z, g03 * H0.w);
                *(float4*)&sRH[rA1 * HS + jA] =
                    make_float4(g10 * H1.x, g11 * H1.y, g12 * H1.z, g13 * H1.w);
            } else {
                *(float4*)&sZ[rA0 * HS + jA] = make_float4(g00, g01, g02, g03);
                *(float4*)&sZ[rA1 * HS + jA] = make_float4(g10, g11, g12, g13);
            }
        }
        __syncthreads();

        // ---------------- Pass B: candidate:  (r*h) @ W_hh ----------------
        ull bA0 = 0, bA1 = 0;   // (cB, cB+1) for rows rA0, rA1
#pragma unroll
        for (int k4 = 0; k4 < 64; k4 += 4) {
            float r0v[4], r1v[4];
            *(float4*)r0v = *(const float4*)&sRH[rA0 * HS + k4];
            *(float4*)r1v = *(const float4*)&sRH[rA1 * HS + k4];
#pragma unroll
            for (int kk = 0; kk < 4; kk++) {
                ull wv = *(const ull*)&wB[(k4 + kk) * 64];
                bA0 = fma2(dup2(r0v[kk]), wv, bA0);
                bA1 = fma2(dup2(r1v[kk]), wv, bA1);
            }
        }
        {
            float x00, x01, x10, x11;
            unpack2(bA0, x00, x01);
            unpack2(bA1, x10, x11);
            float2 tb0 = *(const float2*)&sTab[4096 + cc0 * 64 + cB];
            float2 tb1 = *(const float2*)&sTab[4096 + cc1 * 64 + cB];
            float cv00 = tanhfast(x00 + tb0.x + pbB0.x);
            float cv01 = tanhfast(x01 + tb0.y + pbB0.y);
            float cv10 = tanhfast(x10 + tb1.x + pbB1.x);
            float cv11 = tanhfast(x11 + tb1.y + pbB1.y);
            float2 z0 = *(const float2*)&sZ[rA0 * HS + cB];
            float2 z1 = *(const float2*)&sZ[rA1 * HS + cB];
            float2 h0 = *(const float2*)&sH[rA0 * HS + cB];
            float2 h1 = *(const float2*)&sH[rA1 * HS + cB];
            float hn00 = fmaf(z0.x, cv00 - h0.x, h0.x);
            float hn01 = fmaf(z0.y, cv01 - h0.y, h0.y);
            float hn10 = fmaf(z1.x, cv10 - h1.x, h1.x);
            float hn11 = fmaf(z1.y, cv11 - h1.y, h1.y);
            *(float2*)&sH[rA0 * HS + cB] = make_float2(hn00, hn01);
            *(float2*)&sH[rA1 * HS + cB] = make_float2(hn10, hn11);
        }
        __syncthreads();

        // ---------------- Pass C: logits + log-softmax NLL ----------------
        ull cP = 0;
        const float* hc0 = sH + (2 * w) * HS;
        const float* hc1 = sH + (2 * w + 1) * HS;
#pragma unroll
        for (int k4 = 0; k4 < 64; k4 += 4) {
            float4 A = *(const float4*)&hc0[k4];
            float4 B = *(const float4*)&hc1[k4];
            ull hp[4];
            hp[0] = pack2(A.x, B.x); hp[1] = pack2(A.y, B.y);
            hp[2] = pack2(A.z, B.z); hp[3] = pack2(A.w, B.w);
#pragma unroll
            for (int kk = 0; kk < 4; kk++) {
                ull wd = dup2(sWp[(k4 + kk) * 32 + v]);
                cP = fma2(hp[kk], wd, cP);
            }
        }
        float accC[2];
        unpack2(cP, accC[0], accC[1]);   // rows 2w, 2w+1
#pragma unroll
        for (int r = 0; r < 2; r++) {
            int row = 2 * w + r;
            float lg = accC[r] + bp;
            out[((long long)(b0 + row) * TT + t) * VV + v] = lg;
            int tgt = sCS[row * T1 + t + 1];
            float m = lg;
#pragma unroll
            for (int o = 16; o > 0; o >>= 1)
                m = fmaxf(m, __shfl_xor_sync(0xffffffffu, m, o));
            float s = __expf(lg - m);
#pragma unroll
            for (int o = 16; o > 0; o >>= 1)
                s += __shfl_xor_sync(0xffffffffu, s, o);
            float lt = __shfl_sync(0xffffffffu, lg, tgt);
            if (v == 0 && tgt != 0) {
                nllAcc += m + __logf(s) - lt;
                cntAcc += 1.f;
            }
        }
        // no barrier here: C reads only sH (post-B bar); next-A reads sH and
        // writes sRH/sZ (ordered vs B by post-A bar); next-B's sH writes are
        // ordered after everyone's C by the next post-A barrier.
    }

    // deterministic per-block loss partials
    if (v == 0) { sRed[w] = nllAcc; sRed[8 + w] = cntAcc; }
    __syncthreads();
    if (tid == 0) {
        float aa = 0.f, c = 0.f;
#pragma unroll
        for (int i = 0; i < 8; i++) { aa += sRed[i]; c += sRed[8 + i]; }
        g_part[blockIdx.x] = aa;
        g_part[NBLK + blockIdx.x] = c;
    }
}

// -------------------------------------------------------------------------
// Kernel 4: final loss reduction (deterministic tree)
// -------------------------------------------------------------------------
__global__ void loss_kernel(float* __restrict__ out, long long out_size) {
    __shared__ float sa[NBLK], sc[NBLK];
    int tid = threadIdx.x;
    sa[tid] = g_part[tid];
    sc[tid] = g_part[NBLK + tid];
    __syncthreads();
    for (int s = NBLK / 2; s > 0; s >>= 1) {
        if (tid < s) { sa[tid] += sa[tid + s]; sc[tid] += sc[tid + s]; }
        __syncthreads();
    }
    if (tid == 0 && out_size > (long long)BB * TT * VV)
        out[out_size - 1] = sa[0] / fmaxf(sc[0], 1.f);
}

// -------------------------------------------------------------------------
extern "C" void kernel_launch(void* const* d_in, const int* in_sizes, int n_in,
                              void* d_out, int out_size) {
    const float* phon  = (const float*)d_in[0];
    const void*  cs    = d_in[1];
    const float* emb   = (const float*)d_in[2];
    const float* Wrx   = (const float*)d_in[3];
    const float* brx   = (const float*)d_in[4];
    const float* Wrh   = (const float*)d_in[5];
    const float* brh   = (const float*)d_in[6];
    const float* Wzx   = (const float*)d_in[7];
    const float* bzx   = (const float*)d_in[8];
    const float* Wzh   = (const float*)d_in[9];
    const float* bzh   = (const float*)d_in[10];
    const float* Whx   = (const float*)d_in[11];
    const float* bhx   = (const float*)d_in[12];
    const float* Whh   = (const float*)d_in[13];
    const float* bhh   = (const float*)d_in[14];
    const float* Wproj = (const float*)d_in[15];
    const float* bproj = (const float*)d_in[16];
    float* out = (float*)d_out;

    (void)cudaFuncSetAttribute(gru_kernel,
                               cudaFuncAttributeMaxDynamicSharedMemorySize,
                               SMEM_BYTES);

    detect_kernel<<<1, 1024>>>((const int*)cs, BB * T1);
    convert_kernel<<<(BB * T1 + 255) / 256, 256>>>(cs);
    table_kernel<<<24, 256>>>(emb, Wrx, Wzx, Whx);
    phonb_kernel<<<(3 * BB * 32 + 255) / 256, 256>>>(phon, Wrx, Wzx, Whx,
                                                     brx, brh, bzx, bzh, bhx, bhh);
    gru_kernel<<<NBLK, 256, SMEM_BYTES>>>(Wrh, Wzh, Whh, Wproj, bproj, out);
    loss_kernel<<<1, 256>>>(out, (long long)out_size);
}

// round 15
// speedup vs baseline: 1.3464x; 1.1561x over previous
#include <cuda_runtime.h>

#define BB 4096
#define TT 64
#define T1 65
#define HH 64
#define PP 50
#define VV 32
#define BT 16
#define NBLK (BB / BT) /* 256 */
#define NROWS (BB * TT) /* 262144 logit rows */
#define NLLB 1024       /* nll blocks */

#define SMEM_FLOATS 24608
#define SMEM_BYTES (SMEM_FLOATS * 4)

typedef unsigned long long ull;

// scratch (device globals; no allocation allowed)
__device__ float g_table[3 * 32 * 64];
__device__ float g_phonb[3 * BB * 64];
__device__ float g_part2[NLLB];
__device__ float g_cnt2[NLLB];
__device__ int   g_cs[BB * T1];
__device__ int   g_flag;

// ---- helpers --------------------------------------------------------------
__device__ __forceinline__ ull fma2(ull a, ull b, ull c) {
    asm("fma.rn.f32x2 %0, %1, %2, %0;" : "+l"(c) : "l"(a), "l"(b));
    return c;
}
__device__ __forceinline__ ull pack2(float a, float b) {
    ull d;
    asm("mov.b64 %0, {%1, %2};" : "=l"(d)
        : "r"(__float_as_uint(a)), "r"(__float_as_uint(b)));
    return d;
}
__device__ __forceinline__ ull dup2(float v) {
    ull d;
    unsigned int u = __float_as_uint(v);
    asm("mov.b64 %0, {%1, %1};" : "=l"(d) : "r"(u));
    return d;
}
__device__ __forceinline__ void unpack2(ull d, float& a, float& b) {
    unsigned int x, y;
    asm("mov.b64 {%0, %1}, %2;" : "=r"(x), "=r"(y) : "l"(d));
    a = __uint_as_float(x);
    b = __uint_as_float(y);
}
__device__ __forceinline__ float sigf(float x) {
    float e = __expf(-x);
    return __fdividef(1.f, 1.f + e);
}
__device__ __forceinline__ float tanhfast(float x) {
    float e = __expf(-2.f * x);
    return __fdividef(2.f, 1.f + e) - 1.f;
}
// pair-scoped barrier: warps {2m, 2m+1} (64 threads), ids 1..4
__device__ __forceinline__ void pair_bar(int m) {
    asm volatile("bar.sync %0, 64;" :: "r"(m + 1) : "memory");
}

// -------------------------------------------------------------------------
// Kernel 0a: detect char_seq dtype (odd-word OR; 0 <=> int64 storage)
// -------------------------------------------------------------------------
__global__ void detect_kernel(const int* __restrict__ src, int nelem) {
    __shared__ int sh[1024];
    int acc = 0;
    for (int i = threadIdx.x; i < nelem; i += 1024)
        if (i & 1) acc |= src[i];
    sh[threadIdx.x] = acc;
    __syncthreads();
    for (int s = 512; s > 0; s >>= 1) {
        if (threadIdx.x < s) sh[threadIdx.x] |= sh[threadIdx.x + s];
        __syncthreads();
    }
    if (threadIdx.x == 0) g_flag = sh[0];
}

__global__ void convert_kernel(const void* __restrict__ src) {
    int i = blockIdx.x * blockDim.x + threadIdx.x;
    if (i >= BB * T1) return;
    if (g_flag != 0) g_cs[i] = ((const int*)src)[i];
    else             g_cs[i] = (int)((const long long*)src)[i];
}

// -------------------------------------------------------------------------
// Kernel 1: char table  table[g][c][j] = sum_k emb[c][k] * W_gx[k][j]
// -------------------------------------------------------------------------
__global__ void table_kernel(const float* __restrict__ emb,
                             const float* __restrict__ Wrx,
                             const float* __restrict__ Wzx,
                             const float* __restrict__ Whx) {
    int idx = blockIdx.x * blockDim.x + threadIdx.x;
    if (idx >= 3 * 32 * 64) return;
    int g = idx >> 11;
    int rem = idx & 2047;
    int c = rem >> 6;
    int j = rem & 63;
    const float* W = (g == 0) ? Wrx : ((g == 1) ? Wzx : Whx);
    const float* e = emb + c * HH;
    float acc = 0.f;
#pragma unroll
    for (int k = 0; k < HH; k++) acc = fmaf(e[k], W[k * HH + j], acc);
    g_table[idx] = acc;
}

// -------------------------------------------------------------------------
// Kernel 2: phon part (f32x2 over j-pairs)
// -------------------------------------------------------------------------
__global__ void phonb_kernel(const float* __restrict__ phon,
                             const float* __restrict__ Wrx,
                             const float* __restrict__ Wzx,
                             const float* __restrict__ Whx,
                             const float* __restrict__ brx,
                             const float* __restrict__ brh,
                             const float* __restrict__ bzx,
                             const float* __restrict__ bzh,
                             const float* __restrict__ bhx,
                             const float* __restrict__ bhh) {
    int idx = blockIdx.x * blockDim.x + threadIdx.x;
    if (idx >= 3 * BB * 32) return;
    int g = idx / (BB * 32);
    int rem = idx - g * (BB * 32);
    int b = rem >> 5;
    int jp = rem & 31;
    const float* W  = (g == 0) ? Wrx : ((g == 1) ? Wzx : Whx);
    const float* bx = (g == 0) ? brx : ((g == 1) ? bzx : bhx);
    const float* bh = (g == 0) ? brh : ((g == 1) ? bzh : bhh);
    float2 x2 = *(const float2*)&bx[jp * 2];
    float2 h2 = *(const float2*)&bh[jp * 2];
    ull acc = pack2(x2.x + h2.x, x2.y + h2.y);
    const float* ph = phon + b * PP;
#pragma unroll
    for (int p = 0; p < PP; p++) {
        ull d = dup2(ph[p]);
        ull w = *(const ull*)&W[(HH + p) * HH + jp * 2];
        acc = fma2(d, w, acc);
    }
    float a0, a1;
    unpack2(acc, a0, a1);
    *(float2*)&g_phonb[g * (BB * 64) + b * 64 + jp * 2] = make_float2(a0, a1);
}

// -------------------------------------------------------------------------
// Kernel 3: persistent fused GRU recurrence + projection.
//   EXACT round-11 structure (373.2us measured): row-pair f32x2 GEMMs,
//   pair-scoped barriers. Softmax/NLL evicted to nll_kernel — pass C now
//   ends at the logit store (no shuffles, no expf, no loss epilogue).
// -------------------------------------------------------------------------
__global__ __launch_bounds__(256, 2)
void gru_kernel(const float* __restrict__ Wrh,
                const float* __restrict__ Wzh,
                const float* __restrict__ Whh,
                const float* __restrict__ Wproj,
                const float* __restrict__ bproj,
                float* __restrict__ out) {
    extern __shared__ float sm[];
    float* sWa  = sm;            // [64][128]: W_rh | W_zh, k-major
    float* sWh  = sm + 8192;     // [64][64]
    float* sWp  = sm + 12288;    // [64][32]
    float* sTab = sm + 14336;    // [3][32][64]
    float* sHp  = sm + 20480;    // [8 pairs][64 k][2]
    float* sRHp = sm + 21504;    // [8][64][2]  r*h
    float* sZp  = sm + 22528;    // [8][64][2]  z
    int*   sCS  = (int*)(sm + 23552); // [16][65]

    const int tid = threadIdx.x;
    const int b0 = blockIdx.x * BT;

    // cooperative init
    for (int i = tid; i < 8192; i += 256) {
        int k = i >> 7, j = i & 127;
        sWa[i] = (j < 64) ? Wrh[k * 64 + j] : Wzh[k * 64 + (j - 64)];
    }
    for (int i = tid; i < 4096; i += 256) sWh[i] = Whh[i];
    for (int i = tid; i < 2048; i += 256) sWp[i] = Wproj[i];
    for (int i = tid; i < 6144; i += 256) sTab[i] = g_table[i];
    for (int i = tid; i < BT * T1; i += 256) {
        int r = i / T1, t = i - r * T1;
        sCS[i] = g_cs[(b0 + r) * T1 + t];
    }
    for (int i = tid; i < BT * 64; i += 256) sHp[i] = 0.f;

    // thread mappings
    const int rq = tid >> 6;         // 0..3 = pair-group id (rows 4rq..4rq+3)
    const int cg = tid & 63;         // 0..63
    const int j0 = cg << 1;          // 0..126 (pass A col pair over [r|z])
    const int gA = (j0 >= 64) ? 1 : 0;
    const int jjA = j0 & 63;
    const int v  = tid & 31;         // pass C vocab col
    const int rg = tid >> 5;         // 0..7 -> pair rg (rows 2rg, 2rg+1)

    const int pA0 = 2 * rq, pA1 = 2 * rq + 1;
    const float* hp0 = sHp + pA0 * 128;
    const float* hp1 = sHp + pA1 * 128;
    const float* rp0 = sRHp + pA0 * 128;
    const float* rp1 = sRHp + pA1 * 128;

    float pbA[4][2], pbB[4];
#pragma unroll
    for (int r = 0; r < 4; r++) {
        int base = gA * (BB * 64) + (b0 + 4 * rq + r) * 64 + jjA;
        pbA[r][0] = g_phonb[base];
        pbA[r][1] = g_phonb[base + 1];
        pbB[r] = g_phonb[2 * (BB * 64) + (b0 + 4 * rq + r) * 64 + cg];
    }
    const float bp = bproj[v];

    __syncthreads();

    for (int t = 0; t < TT; t++) {
        int cc[4];
#pragma unroll
        for (int r = 0; r < 4; r++) cc[r] = sCS[(4 * rq + r) * T1 + t];

        // ---------------- Pass A: r,z gates:  h @ [W_rh|W_zh] -------------
        ull aP0c0 = 0, aP0c1 = 0, aP1c0 = 0, aP1c1 = 0;
#pragma unroll
        for (int k4 = 0; k4 < 64; k4 += 4) {
            float4 A0 = *(const float4*)(hp0 + 2 * k4);
            float4 A1 = *(const float4*)(hp0 + 2 * k4 + 4);
            float4 B0 = *(const float4*)(hp1 + 2 * k4);
            float4 B1 = *(const float4*)(hp1 + 2 * k4 + 4);
            ull h0[4], h1[4];
            h0[0] = pack2(A0.x, A0.y); h0[1] = pack2(A0.z, A0.w);
            h0[2] = pack2(A1.x, A1.y); h0[3] = pack2(A1.z, A1.w);
            h1[0] = pack2(B0.x, B0.y); h1[1] = pack2(B0.z, B0.w);
            h1[2] = pack2(B1.x, B1.y); h1[3] = pack2(B1.z, B1.w);
#pragma unroll
            for (int kk = 0; kk < 4; kk++) {
                float2 w = *(const float2*)&sWa[(k4 + kk) * 128 + j0];
                ull wx = dup2(w.x);
                ull wy = dup2(w.y);
                aP0c0 = fma2(h0[kk], wx, aP0c0);
                aP0c1 = fma2(h0[kk], wy, aP0c1);
                aP1c0 = fma2(h1[kk], wx, aP1c0);
                aP1c1 = fma2(h1[kk], wy, aP1c1);
            }
        }
        {
            float a00, a10, a01, a11, a20, a30, a21, a31;
            unpack2(aP0c0, a00, a10);
            unpack2(aP0c1, a01, a11);
            unpack2(aP1c0, a20, a30);
            unpack2(aP1c1, a21, a31);
            const float* tg_ = sTab + gA * 2048;
            float2 t0 = *(const float2*)&tg_[cc[0] * 64 + jjA];
            float2 t1 = *(const float2*)&tg_[cc[1] * 64 + jjA];
            float2 t2 = *(const float2*)&tg_[cc[2] * 64 + jjA];
            float2 t3 = *(const float2*)&tg_[cc[3] * 64 + jjA];
            float g00 = sigf(a00 + t0.x + pbA[0][0]);
            float g01 = sigf(a01 + t0.y + pbA[0][1]);
            float g10 = sigf(a10 + t1.x + pbA[1][0]);
            float g11 = sigf(a11 + t1.y + pbA[1][1]);
            float g20 = sigf(a20 + t2.x + pbA[2][0]);
            float g21 = sigf(a21 + t2.y + pbA[2][1]);
            float g30 = sigf(a30 + t3.x + pbA[3][0]);
            float g31 = sigf(a31 + t3.y + pbA[3][1]);
            if (gA == 0) {
                float4 H0 = *(const float4*)(hp0 + 2 * jjA);
                float4 H1 = *(const float4*)(hp1 + 2 * jjA);
                *(float4*)(sRHp + pA0 * 128 + 2 * jjA) =
                    make_float4(g00 * H0.x, g10 * H0.y, g01 * H0.z, g11 * H0.w);
                *(float4*)(sRHp + pA1 * 128 + 2 * jjA) =
                    make_float4(g20 * H1.x, g30 * H1.y, g21 * H1.z, g31 * H1.w);
            } else {
                *(float4*)(sZp + pA0 * 128 + 2 * jjA) = make_float4(g00, g10, g01, g11);
                *(float4*)(sZp + pA1 * 128 + 2 * jjA) = make_float4(g20, g30, g21, g31);
            }
        }
        pair_bar(rq);

        // ---------------- Pass B: candidate:  (r*h) @ W_hh ----------------
        ull bP0 = 0, bP1 = 0;
#pragma unroll
        for (int k4 = 0; k4 < 64; k4 += 4) {
            float4 R0 = *(const float4*)(rp0 + 2 * k4);
            float4 R1 = *(const float4*)(rp0 + 2 * k4 + 4);
            float4 S0 = *(const float4*)(rp1 + 2 * k4);
            float4 S1 = *(const float4*)(rp1 + 2 * k4 + 4);
            ull r0[4], r1[4];
            r0[0] = pack2(R0.x, R0.y); r0[1] = pack2(R0.z, R0.w);
            r0[2] = pack2(R1.x, R1.y); r0[3] = pack2(R1.z, R1.w);
            r1[0] = pack2(S0.x, S0.y); r1[1] = pack2(S0.z, S0.w);
            r1[2] = pack2(S1.x, S1.y); r1[3] = pack2(S1.z, S1.w);
#pragma unroll
            for (int kk = 0; kk < 4; kk++) {
                ull wd = dup2(sWh[(k4 + kk) * 64 + cg]);
                bP0 = fma2(r0[kk], wd, bP0);
                bP1 = fma2(r1[kk], wd, bP1);
            }
        }
        {
            float x0, x1, x2, x3;
            unpack2(bP0, x0, x1);
            unpack2(bP1, x2, x3);
            float cv0 = tanhfast(x0 + sTab[4096 + cc[0] * 64 + cg] + pbB[0]);
            float cv1 = tanhfast(x1 + sTab[4096 + cc[1] * 64 + cg] + pbB[1]);
            float cv2 = tanhfast(x2 + sTab[4096 + cc[2] * 64 + cg] + pbB[2]);
            float cv3 = tanhfast(x3 + sTab[4096 + cc[3] * 64 + cg] + pbB[3]);
            float2 Z0 = *(const float2*)(sZp + pA0 * 128 + 2 * cg);
            float2 Z1 = *(const float2*)(sZp + pA1 * 128 + 2 * cg);
            float2 Hh0 = *(const float2*)(hp0 + 2 * cg);
            float2 Hh1 = *(const float2*)(hp1 + 2 * cg);
            float hn0 = fmaf(Z0.x, cv0 - Hh0.x, Hh0.x);
            float hn1 = fmaf(Z0.y, cv1 - Hh0.y, Hh0.y);
            float hn2 = fmaf(Z1.x, cv2 - Hh1.x, Hh1.x);
            float hn3 = fmaf(Z1.y, cv3 - Hh1.y, Hh1.y);
            *(float2*)(sHp + pA0 * 128 + 2 * cg) = make_float2(hn0, hn1);
            *(float2*)(sHp + pA1 * 128 + 2 * cg) = make_float2(hn2, hn3);
        }
        pair_bar(rq);

        // ---------------- Pass C: logits only ------------------------------
        ull cP = 0;
        const float* hc = sHp + rg * 128;
#pragma unroll
        for (int k4 = 0; k4 < 64; k4 += 4) {
            float4 A = *(const float4*)(hc + 2 * k4);
            float4 B = *(const float4*)(hc + 2 * k4 + 4);
            ull hp[4];
            hp[0] = pack2(A.x, A.y); hp[1] = pack2(A.z, A.w);
            hp[2] = pack2(B.x, B.y); hp[3] = pack2(B.z, B.w);
#pragma unroll
            for (int kk = 0; kk < 4; kk++) {
                ull wd = dup2(sWp[(k4 + kk) * 32 + v]);
                cP = fma2(hp[kk], wd, cP);
            }
        }
        float c0, c1;
        unpack2(cP, c0, c1);   // rows 2rg, 2rg+1
        out[((long long)(b0 + 2 * rg) * TT + t) * VV + v] = c0 + bp;
        out[((long long)(b0 + 2 * rg + 1) * TT + t) * VV + v] = c1 + bp;
        // pass C reads only pair rg's sHp rows (written in pass B by this
        // same pair); next pass A likewise -> no barrier needed here.
    }
}

// -------------------------------------------------------------------------
// Kernel 4: masked NLL from logits (one (b,t) row per thread, no shuffles)
// -------------------------------------------------------------------------
__global__ __launch_bounds__(256)
void nll_kernel(const float* __restrict__ out) {
    __shared__ float sa[256], sc[256];
    const int tid = threadIdx.x;
    const long long R = (long long)blockIdx.x * 256 + tid;
    const int b = (int)(R >> 6), t = (int)(R & 63);
    const float* lp = out + R * VV;
    float4 q[8];
#pragma unroll
    for (int i = 0; i < 8; i++) q[i] = *(const float4*)&lp[4 * i];
    float m = q[0].x;
#pragma unroll
    for (int i = 0; i < 8; i++) {
        m = fmaxf(m, fmaxf(fmaxf(q[i].x, q[i].y), fmaxf(q[i].z, q[i].w)));
    }
    float s = 0.f;
#pragma unroll
    for (int i = 0; i < 8; i++) {
        s += __expf(q[i].x - m) + __expf(q[i].y - m)
           + __expf(q[i].z - m) + __expf(q[i].w - m);
    }
    int tgt = g_cs[b * T1 + t + 1];
    float nll = 0.f, cnt = 0.f;
    if (tgt != 0) {
        float lt = ((const float*)q)[tgt];
        nll = m + __logf(s) - lt;
        cnt = 1.f;
    }
    sa[tid] = nll;
    sc[tid] = cnt;
    __syncthreads();
    for (int st = 128; st > 0; st >>= 1) {
        if (tid < st) { sa[tid] += sa[tid + st]; sc[tid] += sc[tid + st]; }
        __syncthreads();
    }
    if (tid == 0) { g_part2[blockIdx.x] = sa[0]; g_cnt2[blockIdx.x] = sc[0]; }
}

// -------------------------------------------------------------------------
// Kernel 5: final deterministic loss reduction over 1024 partials
// -------------------------------------------------------------------------
__global__ void loss_kernel(float* __restrict__ out, long long out_size) {
    __shared__ float sa[NLLB], sc[NLLB];
    int tid = threadIdx.x;
    sa[tid] = g_part2[tid];
    sc[tid] = g_cnt2[tid];
    __syncthreads();
    for (int s = NLLB / 2; s > 0; s >>= 1) {
        if (tid < s) { sa[tid] += sa[tid + s]; sc[tid] += sc[tid + s]; }
        __syncthreads();
    }
    if (tid == 0 && out_size > (long long)BB * TT * VV)
        out[out_size - 1] = sa[0] / fmaxf(sc[0], 1.f);
}

// -------------------------------------------------------------------------
extern "C" void kernel_launch(void* const* d_in, const int* in_sizes, int n_in,
                              void* d_out, int out_size) {
    const float* phon  = (const float*)d_in[0];
    const void*  cs    = d_in[1];
    const float* emb   = (const float*)d_in[2];
    const float* Wrx   = (const float*)d_in[3];
    const float* brx   = (const float*)d_in[4];
    const float* Wrh   = (const float*)d_in[5];
    const float* brh   = (const float*)d_in[6];
    const float* Wzx   = (const float*)d_in[7];
    const float* bzx   = (const float*)d_in[8];
    const float* Wzh   = (const float*)d_in[9];
    const float* bzh   = (const float*)d_in[10];
    const float* Whx   = (const float*)d_in[11];
    const float* bhx   = (const float*)d_in[12];
    const float* Whh   = (const float*)d_in[13];
    const float* bhh   = (const float*)d_in[14];
    const float* Wproj = (const float*)d_in[15];
    const float* bproj = (const float*)d_in[16];
    float* out = (float*)d_out;

    (void)cudaFuncSetAttribute(gru_kernel,
                               cudaFuncAttributeMaxDynamicSharedMemorySize,
                               SMEM_BYTES);

    detect_kernel<<<1, 1024>>>((const int*)cs, BB * T1);
    convert_kernel<<<(BB * T1 + 255) / 256, 256>>>(cs);
    table_kernel<<<24, 256>>>(emb, Wrx, Wzx, Whx);
    phonb_kernel<<<(3 * BB * 32 + 255) / 256, 256>>>(phon, Wrx, Wzx, Whx,
                                                     brx, brh, bzx, bzh, bhx, bhh);
    gru_kernel<<<NBLK, 256, SMEM_BYTES>>>(Wrh, Wzh, Whh, Wproj, bproj, out);
    nll_kernel<<<NLLB, 256>>>(out);
    loss_kernel<<<1, NLLB>>>(out, (long long)out_size);
}

// round 17
// speedup vs baseline: 1.4530x; 1.0792x over previous
#include <cuda_runtime.h>

#define BB 4096
#define TT 64
#define T1 65
#define HH 64
#define PP 50
#define VV 32
#define BT 28            /* rows per block */
#define NG 7             /* pair-groups per block (4 rows each) */
#define GRID_G 147       /* ceil(4096/28): one block per SM */
#define THREADS_G 448    /* NG * 64 */
#define NLLB 1024        /* nll blocks */

#define SMEM_FLOATS 27680
#define SMEM_BYTES (SMEM_FLOATS * 4)

typedef unsigned long long ull;

// scratch (device globals; no allocation allowed)
__device__ float g_table[3 * 32 * 64];
__device__ float g_phonb[3 * BB * 64];
__device__ float g_part2[NLLB];
__device__ float g_cnt2[NLLB];
__device__ int   g_cs[BB * T1];
__device__ int   g_flag;

// ---- helpers --------------------------------------------------------------
__device__ __forceinline__ ull fma2(ull a, ull b, ull c) {
    asm("fma.rn.f32x2 %0, %1, %2, %0;" : "+l"(c) : "l"(a), "l"(b));
    return c;
}
__device__ __forceinline__ ull pack2(float a, float b) {
    ull d;
    asm("mov.b64 %0, {%1, %2};" : "=l"(d)
        : "r"(__float_as_uint(a)), "r"(__float_as_uint(b)));
    return d;
}
__device__ __forceinline__ ull dup2(float v) {
    ull d;
    unsigned int u = __float_as_uint(v);
    asm("mov.b64 %0, {%1, %1};" : "=l"(d) : "r"(u));
    return d;
}
__device__ __forceinline__ void unpack2(ull d, float& a, float& b) {
    unsigned int x, y;
    asm("mov.b64 {%0, %1}, %2;" : "=r"(x), "=r"(y) : "l"(d));
    a = __uint_as_float(x);
    b = __uint_as_float(y);
}
__device__ __forceinline__ float sigf(float x) {
    float e = __expf(-x);
    return __fdividef(1.f, 1.f + e);
}
__device__ __forceinline__ float tanhfast(float x) {
    float e = __expf(-2.f * x);
    return __fdividef(2.f, 1.f + e) - 1.f;
}
// pair-scoped barrier: warps {2m, 2m+1} (64 threads), ids 1..NG
__device__ __forceinline__ void pair_bar(int m) {
    asm volatile("bar.sync %0, 64;" :: "r"(m + 1) : "memory");
}

// -------------------------------------------------------------------------
// Kernel 0a: detect char_seq dtype (odd-word OR; 0 <=> int64 storage)
// -------------------------------------------------------------------------
__global__ void detect_kernel(const int* __restrict__ src, int nelem) {
    __shared__ int sh[1024];
    int acc = 0;
    for (int i = threadIdx.x; i < nelem; i += 1024)
        if (i & 1) acc |= src[i];
    sh[threadIdx.x] = acc;
    __syncthreads();
    for (int s = 512; s > 0; s >>= 1) {
        if (threadIdx.x < s) sh[threadIdx.x] |= sh[threadIdx.x + s];
        __syncthreads();
    }
    if (threadIdx.x == 0) g_flag = sh[0];
}

__global__ void convert_kernel(const void* __restrict__ src) {
    int i = blockIdx.x * blockDim.x + threadIdx.x;
    if (i >= BB * T1) return;
    if (g_flag != 0) g_cs[i] = ((const int*)src)[i];
    else             g_cs[i] = (int)((const long long*)src)[i];
}

// -------------------------------------------------------------------------
// Kernel 1: char table  table[g][c][j] = sum_k emb[c][k] * W_gx[k][j]
// -------------------------------------------------------------------------
__global__ void table_kernel(const float* __restrict__ emb,
                             const float* __restrict__ Wrx,
                             const float* __restrict__ Wzx,
                             const float* __restrict__ Whx) {
    int idx = blockIdx.x * blockDim.x + threadIdx.x;
    if (idx >= 3 * 32 * 64) return;
    int g = idx >> 11;
    int rem = idx & 2047;
    int c = rem >> 6;
    int j = rem & 63;
    const float* W = (g == 0) ? Wrx : ((g == 1) ? Wzx : Whx);
    const float* e = emb + c * HH;
    float acc = 0.f;
#pragma unroll
    for (int k = 0; k < HH; k++) acc = fmaf(e[k], W[k * HH + j], acc);
    g_table[idx] = acc;
}

// -------------------------------------------------------------------------
// Kernel 2: phon part (f32x2 over j-pairs)
// -------------------------------------------------------------------------
__global__ void phonb_kernel(const float* __restrict__ phon,
                             const float* __restrict__ Wrx,
                             const float* __restrict__ Wzx,
                             const float* __restrict__ Whx,
                             const float* __restrict__ brx,
                             const float* __restrict__ brh,
                             const float* __restrict__ bzx,
                             const float* __restrict__ bzh,
                             const float* __restrict__ bhx,
                             const float* __restrict__ bhh) {
    int idx = blockIdx.x * blockDim.x + threadIdx.x;
    if (idx >= 3 * BB * 32) return;
    int g = idx / (BB * 32);
    int rem = idx - g * (BB * 32);
    int b = rem >> 5;
    int jp = rem & 31;
    const float* W  = (g == 0) ? Wrx : ((g == 1) ? Wzx : Whx);
    const float* bx = (g == 0) ? brx : ((g == 1) ? bzx : bhx);
    const float* bh = (g == 0) ? brh : ((g == 1) ? bzh : bhh);
    float2 x2 = *(const float2*)&bx[jp * 2];
    float2 h2 = *(const float2*)&bh[jp * 2];
    ull acc = pack2(x2.x + h2.x, x2.y + h2.y);
    const float* ph = phon + b * PP;
#pragma unroll
    for (int p = 0; p < PP; p++) {
        ull d = dup2(ph[p]);
        ull w = *(const ull*)&W[(HH + p) * HH + jp * 2];
        acc = fma2(d, w, acc);
    }
    float a0, a1;
    unpack2(acc, a0, a1);
    *(float2*)&g_phonb[g * (BB * 64) + b * 64 + jp * 2] = make_float2(a0, a1);
}

// -------------------------------------------------------------------------
// Kernel 3: persistent fused GRU recurrence + projection.
//   Round-15 inner structure (366.7us measured) rebalanced to 28 rows /
//   448 threads / 147 blocks = exactly one block per SM (uniform load,
//   vs 108 SMs pacing at 2 blocks before). 7 pair-groups, barrier ids 1..7.
//   Tail block (146) has 2 valid groups; clamped loads + guarded stores.
//   SMEM MAP (floats): sWa 0..8191 | sWh 8192..12287 | sWp 12288..14335
//     sTab 14336..20479 | sHp 20480..22271 | sRHp 22272..24063
//     sZp 24064..25855 | sCS 25856..27675 (1820 ints)
// -------------------------------------------------------------------------
__global__ __launch_bounds__(THREADS_G, 1)
void gru_kernel(const float* __restrict__ Wrh,
                const float* __restrict__ Wzh,
                const float* __restrict__ Whh,
                const float* __restrict__ Wproj,
                const float* __restrict__ bproj,
                float* __restrict__ out) {
    extern __shared__ float sm[];
    float* sWa  = sm;            // [64][128]: W_rh | W_zh, k-major
    float* sWh  = sm + 8192;     // [64][64]
    float* sWp  = sm + 12288;    // [64][32]
    float* sTab = sm + 14336;    // [3][32][64]
    float* sHp  = sm + 20480;    // [14 pairs][64 k][2]
    float* sRHp = sm + 22272;    // [14][64][2]  r*h
    float* sZp  = sm + 24064;    // [14][64][2]  z
    int*   sCS  = (int*)(sm + 25856); // [28][65]

    const int tid = threadIdx.x;
    const int b0 = blockIdx.x * BT;

    // cooperative init
    for (int i = tid; i < 8192; i += THREADS_G) {
        int k = i >> 7, j = i & 127;
        sWa[i] = (j < 64) ? Wrh[k * 64 + j] : Wzh[k * 64 + (j - 64)];
    }
    for (int i = tid; i < 4096; i += THREADS_G) sWh[i] = Whh[i];
    for (int i = tid; i < 2048; i += THREADS_G) sWp[i] = Wproj[i];
    for (int i = tid; i < 6144; i += THREADS_G) sTab[i] = g_table[i];
    for (int i = tid; i < BT * T1; i += THREADS_G) {
        int r = i / T1, t = i - r * T1;
        int row = b0 + r; if (row > BB - 1) row = BB - 1;
        sCS[i] = g_cs[row * T1 + t];
    }
    for (int i = tid; i < (BT / 2) * 128; i += THREADS_G) sHp[i] = 0.f;

    // thread mappings
    const int rq = tid >> 6;         // 0..6 = pair-group id (rows 4rq..4rq+3)
    const int cg = tid & 63;         // 0..63
    const int j0 = cg << 1;          // 0..126 (pass A col pair over [r|z])
    const int gA = (j0 >= 64) ? 1 : 0;
    const int jjA = j0 & 63;
    const int v  = tid & 31;         // pass C vocab col
    const int rg = tid >> 5;         // 0..13 -> pair rg (rows 2rg, 2rg+1)

    const int pA0 = 2 * rq, pA1 = 2 * rq + 1;
    const float* hp0 = sHp + pA0 * 128;
    const float* hp1 = sHp + pA1 * 128;
    const float* rp0 = sRHp + pA0 * 128;
    const float* rp1 = sRHp + pA1 * 128;

    float pbA[4][2], pbB[4];
#pragma unroll
    for (int r = 0; r < 4; r++) {
        int row = b0 + 4 * rq + r; if (row > BB - 1) row = BB - 1;
        int base = gA * (BB * 64) + row * 64 + jjA;
        pbA[r][0] = g_phonb[base];
        pbA[r][1] = g_phonb[base + 1];
        pbB[r] = g_phonb[2 * (BB * 64) + row * 64 + cg];
    }
    const float bp = bproj[v];
    const bool cvalid = (b0 + 2 * rg) < BB;   // pass C row-pair validity

    __syncthreads();

    for (int t = 0; t < TT; t++) {
        int cc[4];
#pragma unroll
        for (int r = 0; r < 4; r++) cc[r] = sCS[(4 * rq + r) * T1 + t];

        // ---------------- Pass A: r,z gates:  h @ [W_rh|W_zh] -------------
        ull aP0c0 = 0, aP0c1 = 0, aP1c0 = 0, aP1c1 = 0;
#pragma unroll
        for (int k4 = 0; k4 < 64; k4 += 4) {
            float4 A0 = *(const float4*)(hp0 + 2 * k4);
            float4 A1 = *(const float4*)(hp0 + 2 * k4 + 4);
            float4 B0 = *(const float4*)(hp1 + 2 * k4);
            float4 B1 = *(const float4*)(hp1 + 2 * k4 + 4);
            ull h0[4], h1[4];
            h0[0] = pack2(A0.x, A0.y); h0[1] = pack2(A0.z, A0.w);
            h0[2] = pack2(A1.x, A1.y); h0[3] = pack2(A1.z, A1.w);
            h1[0] = pack2(B0.x, B0.y); h1[1] = pack2(B0.z, B0.w);
            h1[2] = pack2(B1.x, B1.y); h1[3] = pack2(B1.z, B1.w);
#pragma unroll
            for (int kk = 0; kk < 4; kk++) {
                float2 w = *(const float2*)&sWa[(k4 + kk) * 128 + j0];
                ull wx = dup2(w.x);
                ull wy = dup2(w.y);
                aP0c0 = fma2(h0[kk], wx, aP0c0);
                aP0c1 = fma2(h0[kk], wy, aP0c1);
                aP1c0 = fma2(h1[kk], wx, aP1c0);
                aP1c1 = fma2(h1[kk], wy, aP1c1);
            }
        }
        {
            float a00, a10, a01, a11, a20, a30, a21, a31;
            unpack2(aP0c0, a00, a10);
            unpack2(aP0c1, a01, a11);
            unpack2(aP1c0, a20, a30);
            unpack2(aP1c1, a21, a31);
            const float* tg_ = sTab + gA * 2048;
            float2 t0 = *(const float2*)&tg_[cc[0] * 64 + jjA];
            float2 t1 = *(const float2*)&tg_[cc[1] * 64 + jjA];
            float2 t2 = *(const float2*)&tg_[cc[2] * 64 + jjA];
            float2 t3 = *(const float2*)&tg_[cc[3] * 64 + jjA];
            float g00 = sigf(a00 + t0.x + pbA[0][0]);
            float g01 = sigf(a01 + t0.y + pbA[0][1]);
            float g10 = sigf(a10 + t1.x + pbA[1][0]);
            float g11 = sigf(a11 + t1.y + pbA[1][1]);
            float g20 = sigf(a20 + t2.x + pbA[2][0]);
            float g21 = sigf(a21 + t2.y + pbA[2][1]);
            float g30 = sigf(a30 + t3.x + pbA[3][0]);
            float g31 = sigf(a31 + t3.y + pbA[3][1]);
            if (gA == 0) {
                float4 H0 = *(const float4*)(hp0 + 2 * jjA);
                float4 H1 = *(const float4*)(hp1 + 2 * jjA);
                *(float4*)(sRHp + pA0 * 128 + 2 * jjA) =
                    make_float4(g00 * H0.x, g10 * H0.y, g01 * H0.z, g11 * H0.w);
                *(float4*)(sRHp + pA1 * 128 + 2 * jjA) =
                    make_float4(g20 * H1.x, g30 * H1.y, g21 * H1.z, g31 * H1.w);
            } else {
                *(float4*)(sZp + pA0 * 128 + 2 * jjA) = make_float4(g00, g10, g01, g11);
                *(float4*)(sZp + pA1 * 128 + 2 * jjA) = make_float4(g20, g30, g21, g31);
            }
        }
        pair_bar(rq);

        // ---------------- Pass B: candidate:  (r*h) @ W_hh ----------------
        ull bP0 = 0, bP1 = 0;
#pragma unroll
        for (int k4 = 0; k4 < 64; k4 += 4) {
            float4 R0 = *(const float4*)(rp0 + 2 * k4);
            float4 R1 = *(const float4*)(rp0 + 2 * k4 + 4);
            float4 S0 = *(const float4*)(rp1 + 2 * k4);
            float4 S1 = *(const float4*)(rp1 + 2 * k4 + 4);
            ull r0[4], r1[4];
            r0[0] = pack2(R0.x, R0.y); r0[1] = pack2(R0.z, R0.w);
            r0[2] = pack2(R1.x, R1.y); r0[3] = pack2(R1.z, R1.w);
            r1[0] = pack2(S0.x, S0.y); r1[1] = pack2(S0.z, S0.w);
            r1[2] = pack2(S1.x, S1.y); r1[3] = pack2(S1.z, S1.w);
#pragma unroll
            for (int kk = 0; kk < 4; kk++) {
                ull wd = dup2(sWh[(k4 + kk) * 64 + cg]);
                bP0 = fma2(r0[kk], wd, bP0);
                bP1 = fma2(r1[kk], wd, bP1);
            }
        }
        {
            float x0, x1, x2, x3;
            unpack2(bP0, x0, x1);
            unpack2(bP1, x2, x3);
            float cv0 = tanhfast(x0 + sTab[4096 + cc[0] * 64 + cg] + pbB[0]);
            float cv1 = tanhfast(x1 + sTab[4096 + cc[1] * 64 + cg] + pbB[1]);
            float cv2 = tanhfast(x2 + sTab[4096 + cc[2] * 64 + cg] + pbB[2]);
            float cv3 = tanhfast(x3 + sTab[4096 + cc[3] * 64 + cg] + pbB[3]);
            float2 Z0 = *(const float2*)(sZp + pA0 * 128 + 2 * cg);
            float2 Z1 = *(const float2*)(sZp + pA1 * 128 + 2 * cg);
            float2 Hh0 = *(const float2*)(hp0 + 2 * cg);
            float2 Hh1 = *(const float2*)(hp1 + 2 * cg);
            float hn0 = fmaf(Z0.x, cv0 - Hh0.x, Hh0.x);
            float hn1 = fmaf(Z0.y, cv1 - Hh0.y, Hh0.y);
            float hn2 = fmaf(Z1.x, cv2 - Hh1.x, Hh1.x);
            float hn3 = fmaf(Z1.y, cv3 - Hh1.y, Hh1.y);
            *(float2*)(sHp + pA0 * 128 + 2 * cg) = make_float2(hn0, hn1);
            *(float2*)(sHp + pA1 * 128 + 2 * cg) = make_float2(hn2, hn3);
        }
        pair_bar(rq);

        // ---------------- Pass C: logits only ------------------------------
        ull cP = 0;
        const float* hc = sHp + rg * 128;
#pragma unroll
        for (int k4 = 0; k4 < 64; k4 += 4) {
            float4 A = *(const float4*)(hc + 2 * k4);
            float4 B = *(const float4*)(hc + 2 * k4 + 4);
            ull hp[4];
            hp[0] = pack2(A.x, A.y); hp[1] = pack2(A.z, A.w);
            hp[2] = pack2(B.x, B.y); hp[3] = pack2(B.z, B.w);
#pragma unroll
            for (int kk = 0; kk < 4; kk++) {
                ull wd = dup2(sWp[(k4 + kk) * 32 + v]);
                cP = fma2(hp[kk], wd, cP);
            }
        }
        float c0, c1;
        unpack2(cP, c0, c1);   // rows 2rg, 2rg+1
        if (cvalid) {
            out[((long long)(b0 + 2 * rg) * TT + t) * VV + v] = c0 + bp;
            out[((long long)(b0 + 2 * rg + 1) * TT + t) * VV + v] = c1 + bp;
        }
        // pass C reads only pair rg's sHp rows (written in pass B by this
        // same pair); next pass A likewise -> no barrier needed here.
    }
}

// -------------------------------------------------------------------------
// Kernel 4: masked NLL from logits (one (b,t) row per thread, no shuffles)
// -------------------------------------------------------------------------
__global__ __launch_bounds__(256)
void nll_kernel(const float* __restrict__ out) {
    __shared__ float sa[256], sc[256];
    const int tid = threadIdx.x;
    const long long R = (long long)blockIdx.x * 256 + tid;
    const int b = (int)(R >> 6), t = (int)(R & 63);
    const float* lp = out + R * VV;
    float4 q[8];
#pragma unroll
    for (int i = 0; i < 8; i++) q[i] = *(const float4*)&lp[4 * i];
    float m = q[0].x;
#pragma unroll
    for (int i = 0; i < 8; i++) {
        m = fmaxf(m, fmaxf(fmaxf(q[i].x, q[i].y), fmaxf(q[i].z, q[i].w)));
    }
    float s = 0.f;
#pragma unroll
    for (int i = 0; i < 8; i++) {
        s += __expf(q[i].x - m) + __expf(q[i].y - m)
           + __expf(q[i].z - m) + __expf(q[i].w - m);
    }
    int tgt = g_cs[b * T1 + t + 1];
    float nll = 0.f, cnt = 0.f;
    if (tgt != 0) {
        float lt = ((const float*)q)[tgt];
        nll = m + __logf(s) - lt;
        cnt = 1.f;
    }
    sa[tid] = nll;
    sc[tid] = cnt;
    __syncthreads();
    for (int st = 128; st > 0; st >>= 1) {
        if (tid < st) { sa[tid] += sa[tid + st]; sc[tid] += sc[tid + st]; }
        __syncthreads();
    }
    if (tid == 0) { g_part2[blockIdx.x] = sa[0]; g_cnt2[blockIdx.x] = sc[0]; }
}

// -------------------------------------------------------------------------
// Kernel 5: final deterministic loss reduction over 1024 partials
// -------------------------------------------------------------------------
__global__ void loss_kernel(float* __restrict__ out, long long out_size) {
    __shared__ float sa[NLLB], sc[NLLB];
    int tid = threadIdx.x;
    sa[tid] = g_part2[tid];
    sc[tid] = g_cnt2[tid];
    __syncthreads();
    for (int s = NLLB / 2; s > 0; s >>= 1) {
        if (tid < s) { sa[tid] += sa[tid + s]; sc[tid] += sc[tid + s]; }
        __syncthreads();
    }
    if (tid == 0 && out_size > (long long)BB * TT * VV)
        out[out_size - 1] = sa[0] / fmaxf(sc[0], 1.f);
}

// -------------------------------------------------------------------------
extern "C" void kernel_launch(void* const* d_in, const int* in_sizes, int n_in,
                              void* d_out, int out_size) {
    const float* phon  = (const float*)d_in[0];
    const void*  cs    = d_in[1];
    const float* emb   = (const float*)d_in[2];
    const float* Wrx   = (const float*)d_in[3];
    const float* brx   = (const float*)d_in[4];
    const float* Wrh   = (const float*)d_in[5];
    const float* brh   = (const float*)d_in[6];
    const float* Wzx   = (const float*)d_in[7];
    const float* bzx   = (const float*)d_in[8];
    const float* Wzh   = (const float*)d_in[9];
    const float* bzh   = (const float*)d_in[10];
    const float* Whx   = (const float*)d_in[11];
    const float* bhx   = (const float*)d_in[12];
    const float* Whh   = (const float*)d_in[13];
    const float* bhh   = (const float*)d_in[14];
    const float* Wproj = (const float*)d_in[15];
    const float* bproj = (const float*)d_in[16];
    float* out = (float*)d_out;

    (void)cudaFuncSetAttribute(gru_kernel,
                               cudaFuncAttributeMaxDynamicSharedMemorySize,
                               SMEM_BYTES);

    detect_kernel<<<1, 1024>>>((const int*)cs, BB * T1);
    convert_kernel<<<(BB * T1 + 255) / 256, 256>>>(cs);
    table_kernel<<<24, 256>>>(emb, Wrx, Wzx, Whx);
    phonb_kernel<<<(3 * BB * 32 + 255) / 256, 256>>>(phon, Wrx, Wzx, Whx,
                                                     brx, brh, bzx, bzh, bhx, bhh);
    gru_kernel<<<GRID_G, THREADS_G, SMEM_BYTES>>>(Wrh, Wzh, Whh, Wproj, bproj, out);
    nll_kernel<<<NLLB, 256>>>(out);
    loss_kernel<<<1, NLLB>>>(out, (long long)out_size);
}